// round 1
// baseline (speedup 1.0000x reference)
#include <cuda_runtime.h>
#include <math.h>

#define B_DIM 4
#define L_DIM 4096
#define D_DIM 1024
#define NFFT 8192

// ---------------- scratch (static device globals; no allocation) -----------
__device__ float  g_uT[(size_t)B_DIM * D_DIM * L_DIM];   // [B, D, L]  64 MiB
__device__ float  g_vT[(size_t)B_DIM * D_DIM * L_DIM];   // [B, D, L]  64 MiB (reused for yT)
__device__ float2 g_Hf[(size_t)D_DIM * NFFT];            // [D, 8192]  64 MiB
__device__ float2 g_tw[2048];                            // exp(-2pi i k / 8192)

// ---------------- complex helpers ------------------------------------------
__device__ __forceinline__ float2 cadd(float2 a, float2 b) { return make_float2(a.x + b.x, a.y + b.y); }
__device__ __forceinline__ float2 csub(float2 a, float2 b) { return make_float2(a.x - b.x, a.y - b.y); }
__device__ __forceinline__ float2 cmul(float2 a, float2 b) {
    return make_float2(fmaf(a.x, b.x, -a.y * b.y), fmaf(a.x, b.y, a.y * b.x));
}

// ---------------- 8192-pt forward FFT (Stockham DIF, radix-4 + radix-2) ----
// x, y: ping-pong smem buffers of 8192 float2. tw: 2048-entry table in smem.
// 512 threads. Requires __syncthreads() before the call (input staged in x).
// Returns pointer to buffer holding result (always y), natural order.
__device__ float2* fft8192(float2* x, float2* y, const float2* __restrict__ tw, int tid) {
    #pragma unroll 1
    for (int st = 0; st < 6; ++st) {
        const int sh = 2 * st;
        const int s  = 1 << sh;
        #pragma unroll
        for (int r = 0; r < 4; ++r) {
            const int i  = tid + r * 512;
            const int ps = i & ~(s - 1);        // p * s
            float2 a = x[i];
            float2 b = x[i + 2048];
            float2 c = x[i + 4096];
            float2 d = x[i + 6144];
            float2 apc = cadd(a, c), amc = csub(a, c);
            float2 bpd = cadd(b, d), bmd = csub(b, d);
            float2 w1 = tw[ps];
            float2 w2 = cmul(w1, w1);
            float2 w3 = cmul(w1, w2);
            const int o = i + 3 * ps;
            y[o]         = cadd(apc, bpd);
            y[o + s]     = cmul(w1, make_float2(amc.x + bmd.y, amc.y - bmd.x)); // amc - j*bmd
            y[o + 2 * s] = cmul(w2, csub(apc, bpd));
            y[o + 3 * s] = cmul(w3, make_float2(amc.x - bmd.y, amc.y + bmd.x)); // amc + j*bmd
        }
        __syncthreads();
        float2* t = x; x = y; y = t;
    }
    // 6 swaps -> x,y back to original; final radix-2 (n=2, s=4096) into y.
    #pragma unroll
    for (int r = 0; r < 8; ++r) {
        const int i = tid + r * 512;
        float2 a = x[i], b = x[i + 4096];
        y[i]        = cadd(a, b);
        y[i + 4096] = csub(a, b);
    }
    __syncthreads();
    return y;
}

// ---------------- twiddle init ----------------------------------------------
__global__ void twiddle_kernel(float2* __restrict__ tw) {
    int k = blockIdx.x * blockDim.x + threadIdx.x;
    if (k < 2048) {
        float s, c;
        sincospif((float)k / 4096.0f, &s, &c);
        tw[k] = make_float2(c, -s);             // exp(-2pi i k / 8192)
    }
}

// ---------------- filter FFT: Hf[d,:] = FFT(h_filter[:,d] * exp(-0.01 l)) ---
__global__ void filter_kernel(const float* __restrict__ hfilt,
                              const float2* __restrict__ gtw,
                              float2* __restrict__ Hf) {
    extern __shared__ float2 sm[];
    float2* buf0 = sm;
    float2* buf1 = sm + 8192;
    float2* tw   = sm + 16384;
    const int tid = threadIdx.x;
    const int d   = blockIdx.x;

    for (int k = tid; k < 2048; k += 512) tw[k] = gtw[k];
    for (int l = tid; l < 4096; l += 512) {
        float h = hfilt[(size_t)l * D_DIM + d] * expf(-0.01f * (float)l);
        buf0[l]        = make_float2(h, 0.f);
        buf0[l + 4096] = make_float2(0.f, 0.f);
    }
    __syncthreads();
    float2* R = fft8192(buf0, buf1, tw, tid);
    float2* out = Hf + (size_t)d * NFFT;
    for (int k = tid; k < NFFT; k += 512) out[k] = R[k];
}

// ---------------- fused conv + gate per channel -----------------------------
// For channel ch=(b,d): V=FFT(pad(v)); Z=conj(V*Hf[d]); y = real(FFT(Z))/N * u
// (irfft via conj trick: ifft(Z) = conj(fft(conj Z))/N)
__global__ void conv_kernel(const float* __restrict__ vT,
                            const float* __restrict__ uT,
                            const float2* __restrict__ Hf,
                            const float2* __restrict__ gtw,
                            float* __restrict__ yT) {
    extern __shared__ float2 sm[];
    float2* buf0 = sm;
    float2* buf1 = sm + 8192;
    float2* tw   = sm + 16384;
    const int tid = threadIdx.x;
    const int ch  = blockIdx.x;                 // b*D + d
    const int d   = ch & (D_DIM - 1);

    const float* vch = vT + (size_t)ch * L_DIM;
    for (int k = tid; k < 2048; k += 512) tw[k] = gtw[k];
    for (int l = tid; l < 4096; l += 512) {
        buf0[l]        = make_float2(vch[l], 0.f);
        buf0[l + 4096] = make_float2(0.f, 0.f);
    }
    __syncthreads();

    float2* V = fft8192(buf0, buf1, tw, tid);   // V in buf1

    const float2* Hd = Hf + (size_t)d * NFFT;
    for (int k = tid; k < NFFT; k += 512) {
        float2 z = cmul(V[k], Hd[k]);
        buf0[k] = make_float2(z.x, -z.y);       // conj
    }
    __syncthreads();

    float2* R = fft8192(buf0, buf1, tw, tid);   // real part / N = irfft

    const float* uch = uT + (size_t)ch * L_DIM;
    float*       ych = yT + (size_t)ch * L_DIM;
    const float inv = 1.0f / (float)NFFT;
    for (int l = tid; l < 4096; l += 512)
        ych[l] = R[l].x * inv * uch[l];
}

// ---------------- GEMM 1: outT[b,e,l] = sum_d x[b,l,d] W[d,e] + bias[e] -----
// C'[e, m] = W^T x^T; tile 128x128, BK=8, 256 threads, 8x8 per thread.
__global__ void __launch_bounds__(256) gemm_xw_T(
    const float* __restrict__ X, const float* __restrict__ W,
    const float* __restrict__ bias, float* __restrict__ outT) {
    __shared__ float As[8][128];   // As[k][e]
    __shared__ float Bs[8][132];   // Bs[k][m]
    const int tid = threadIdx.x;
    const int tx = tid & 15;       // m direction
    const int ty = tid >> 4;       // e direction
    const int m0 = blockIdx.x * 128;
    const int e0 = blockIdx.y * 128;

    const int a_k = tid >> 5;
    const int a_e = (tid & 31) << 2;
    const int b_m = tid >> 1;
    const int b_k = (tid & 1) << 2;

    float acc[8][8];
    #pragma unroll
    for (int i = 0; i < 8; ++i)
        #pragma unroll
        for (int j = 0; j < 8; ++j) acc[i][j] = 0.f;

    for (int k0 = 0; k0 < 1024; k0 += 8) {
        float4 av = *reinterpret_cast<const float4*>(&W[(size_t)(k0 + a_k) * 1024 + e0 + a_e]);
        float4 bv = *reinterpret_cast<const float4*>(&X[(size_t)(m0 + b_m) * 1024 + k0 + b_k]);
        *reinterpret_cast<float4*>(&As[a_k][a_e]) = av;
        Bs[b_k + 0][b_m] = bv.x;
        Bs[b_k + 1][b_m] = bv.y;
        Bs[b_k + 2][b_m] = bv.z;
        Bs[b_k + 3][b_m] = bv.w;
        __syncthreads();
        #pragma unroll
        for (int kk = 0; kk < 8; ++kk) {
            float4 fa0 = *reinterpret_cast<const float4*>(&As[kk][ty * 8]);
            float4 fa1 = *reinterpret_cast<const float4*>(&As[kk][ty * 8 + 4]);
            float4 fb0 = *reinterpret_cast<const float4*>(&Bs[kk][tx * 8]);
            float4 fb1 = *reinterpret_cast<const float4*>(&Bs[kk][tx * 8 + 4]);
            float fa[8] = {fa0.x, fa0.y, fa0.z, fa0.w, fa1.x, fa1.y, fa1.z, fa1.w};
            float fb[8] = {fb0.x, fb0.y, fb0.z, fb0.w, fb1.x, fb1.y, fb1.z, fb1.w};
            #pragma unroll
            for (int i = 0; i < 8; ++i)
                #pragma unroll
                for (int j = 0; j < 8; ++j)
                    acc[i][j] = fmaf(fa[i], fb[j], acc[i][j]);
        }
        __syncthreads();
    }

    const int bb = m0 >> 12;                    // batch index (tile never straddles b)
    const int l0 = (m0 & 4095) + tx * 8;
    #pragma unroll
    for (int i = 0; i < 8; ++i) {
        const int e = e0 + ty * 8 + i;
        const float be = bias[e];
        float* op = &outT[((size_t)bb * 1024 + e) * 4096 + l0];
        float4 v0 = make_float4(acc[i][0] + be, acc[i][1] + be, acc[i][2] + be, acc[i][3] + be);
        float4 v1 = make_float4(acc[i][4] + be, acc[i][5] + be, acc[i][6] + be, acc[i][7] + be);
        *reinterpret_cast<float4*>(op)     = v0;
        *reinterpret_cast<float4*>(op + 4) = v1;
    }
}

// ---------------- GEMM 2: out[b,l,e] = sum_d yT[b,d,l] Wo[d,e] + bo[e] ------
__global__ void __launch_bounds__(256) gemm_out(
    const float* __restrict__ yT, const float* __restrict__ Wo,
    const float* __restrict__ bo, float* __restrict__ out) {
    __shared__ float As[8][132];   // As[k][m]
    __shared__ float Bs[8][128];   // Bs[k][e]
    const int tid = threadIdx.x;
    const int tx = tid & 15;       // e direction
    const int ty = tid >> 4;       // m direction
    const int m0 = blockIdx.x * 128;
    const int e0 = blockIdx.y * 128;

    const int a_k = tid >> 5;
    const int a_m = (tid & 31) << 2;
    const int bb = m0 >> 12;
    const int lb = m0 & 4095;

    float acc[8][8];
    #pragma unroll
    for (int i = 0; i < 8; ++i)
        #pragma unroll
        for (int j = 0; j < 8; ++j) acc[i][j] = 0.f;

    for (int k0 = 0; k0 < 1024; k0 += 8) {
        float4 av = *reinterpret_cast<const float4*>(
            &yT[((size_t)bb * 1024 + k0 + a_k) * 4096 + lb + a_m]);
        float4 wv = *reinterpret_cast<const float4*>(&Wo[(size_t)(k0 + a_k) * 1024 + e0 + a_m]);
        *reinterpret_cast<float4*>(&As[a_k][a_m]) = av;
        *reinterpret_cast<float4*>(&Bs[a_k][a_m]) = wv;
        __syncthreads();
        #pragma unroll
        for (int kk = 0; kk < 8; ++kk) {
            float4 fa0 = *reinterpret_cast<const float4*>(&As[kk][ty * 8]);
            float4 fa1 = *reinterpret_cast<const float4*>(&As[kk][ty * 8 + 4]);
            float4 fb0 = *reinterpret_cast<const float4*>(&Bs[kk][tx * 8]);
            float4 fb1 = *reinterpret_cast<const float4*>(&Bs[kk][tx * 8 + 4]);
            float fa[8] = {fa0.x, fa0.y, fa0.z, fa0.w, fa1.x, fa1.y, fa1.z, fa1.w};
            float fb[8] = {fb0.x, fb0.y, fb0.z, fb0.w, fb1.x, fb1.y, fb1.z, fb1.w};
            #pragma unroll
            for (int i = 0; i < 8; ++i)
                #pragma unroll
                for (int j = 0; j < 8; ++j)
                    acc[i][j] = fmaf(fa[i], fb[j], acc[i][j]);
        }
        __syncthreads();
    }

    float4 bz0 = *reinterpret_cast<const float4*>(&bo[e0 + tx * 8]);
    float4 bz1 = *reinterpret_cast<const float4*>(&bo[e0 + tx * 8 + 4]);
    #pragma unroll
    for (int i = 0; i < 8; ++i) {
        const int m = m0 + ty * 8 + i;
        float* op = &out[(size_t)m * 1024 + e0 + tx * 8];
        float4 v0 = make_float4(acc[i][0] + bz0.x, acc[i][1] + bz0.y,
                                acc[i][2] + bz0.z, acc[i][3] + bz0.w);
        float4 v1 = make_float4(acc[i][4] + bz1.x, acc[i][5] + bz1.y,
                                acc[i][6] + bz1.z, acc[i][7] + bz1.w);
        *reinterpret_cast<float4*>(op)     = v0;
        *reinterpret_cast<float4*>(op + 4) = v1;
    }
}

// ---------------- launch -----------------------------------------------------
extern "C" void kernel_launch(void* const* d_in, const int* in_sizes, int n_in,
                              void* d_out, int out_size) {
    const float* x   = (const float*)d_in[0];
    const float* Wu  = (const float*)d_in[1];
    const float* bu  = (const float*)d_in[2];
    const float* Wv  = (const float*)d_in[3];
    const float* bv  = (const float*)d_in[4];
    const float* hfl = (const float*)d_in[5];
    const float* Wo  = (const float*)d_in[6];
    const float* bo  = (const float*)d_in[7];
    float* out = (float*)d_out;

    void *pU, *pV, *pH, *pT;
    cudaGetSymbolAddress(&pU, g_uT);
    cudaGetSymbolAddress(&pV, g_vT);
    cudaGetSymbolAddress(&pH, g_Hf);
    cudaGetSymbolAddress(&pT, g_tw);

    const int SMEM_FFT = (16384 + 2048) * (int)sizeof(float2);  // 147456 B
    cudaFuncSetAttribute(filter_kernel, cudaFuncAttributeMaxDynamicSharedMemorySize, SMEM_FFT);
    cudaFuncSetAttribute(conv_kernel,   cudaFuncAttributeMaxDynamicSharedMemorySize, SMEM_FFT);

    twiddle_kernel<<<8, 256>>>((float2*)pT);
    filter_kernel<<<D_DIM, 512, SMEM_FFT>>>(hfl, (const float2*)pT, (float2*)pH);

    dim3 ggrid(128, 8);
    gemm_xw_T<<<ggrid, 256>>>(x, Wu, bu, (float*)pU);
    gemm_xw_T<<<ggrid, 256>>>(x, Wv, bv, (float*)pV);

    conv_kernel<<<B_DIM * D_DIM, 512, SMEM_FFT>>>(
        (const float*)pV, (const float*)pU, (const float2*)pH, (const float2*)pT, (float*)pV);

    gemm_out<<<ggrid, 256>>>((const float*)pV, Wo, bo, out);
}

// round 3
// speedup vs baseline: 2.1226x; 2.1226x over previous
#include <cuda_runtime.h>
#include <math.h>
#include <cstdint>

#define B_DIM 4
#define L_DIM 4096
#define D_DIM 1024
#define NFFT 8192

// ---------------- scratch (static device globals; no allocation) -----------
__device__ float  g_uT[(size_t)B_DIM * D_DIM * L_DIM];   // [B, D, L] (later reused as y[B,L,D])
__device__ float  g_vT[(size_t)B_DIM * D_DIM * L_DIM];   // [B, D, L] (reused for yT)
__device__ float  g_Wt[(size_t)3 * D_DIM * D_DIM];       // Wu^T, Wv^T, Wo^T
__device__ float2 g_Hf[(size_t)D_DIM * NFFT];            // [D, 8192]
__device__ float2 g_tw[2048];                            // exp(-2pi i k / 8192)

// ======================= portable PTX helpers ===============================
__device__ __forceinline__ uint32_t smem_u32(const void* p) {
    uint32_t a;
    asm("{ .reg .u64 t; cvta.to.shared.u64 t, %1; cvt.u32.u64 %0, t; }" : "=r"(a) : "l"(p));
    return a;
}
__device__ __forceinline__ uint32_t f2tf(float f) {
    uint32_t u; asm("cvt.rna.tf32.f32 %0, %1;" : "=r"(u) : "f"(f)); return u;
}
__device__ __forceinline__ void cp_async16(uint32_t saddr, const void* g) {
    asm volatile("cp.async.cg.shared.global [%0], [%1], 16;" :: "r"(saddr), "l"(g));
}
#define CP_COMMIT() asm volatile("cp.async.commit_group;" ::: "memory")
#define CP_WAIT1()  asm volatile("cp.async.wait_group 1;" ::: "memory")

__device__ __forceinline__ void mma_tf32(float* c,
    uint32_t a0, uint32_t a1, uint32_t a2, uint32_t a3, uint32_t b0, uint32_t b1) {
    asm volatile(
        "mma.sync.aligned.m16n8k8.row.col.f32.tf32.tf32.f32 "
        "{%0,%1,%2,%3}, {%4,%5,%6,%7}, {%8,%9}, {%0,%1,%2,%3};"
        : "+f"(c[0]), "+f"(c[1]), "+f"(c[2]), "+f"(c[3])
        : "r"(a0), "r"(a1), "r"(a2), "r"(a3), "r"(b0), "r"(b1));
}

// ======================= tf32 mma.sync GEMM =================================
// C[i][j] = sum_k A[i0+i][k] * B[j0+j][k]    A,B K-major (ld = 1024), K = 1024
// Tile 128x128x32, 8 warps (4 x 2), warp tile 32(M) x 64(N).
// MODE 0: i = e (A = W^T), j = m (B = x). out: outT[b][e][l] + bias[e(row)]
// MODE 1: i = m (A = y),  j = e (B = Wo^T). out: out[m][e] + bias[e(col)]
#define SROW 36                       // smem row stride in floats (128B rows + pad)
#define GEMM_SMEM_BYTES 73728         // 4 buffers * 128*36*4

template <int MODE>
__global__ void __launch_bounds__(256, 2) gemm_mma(
    const float* __restrict__ Ag, const float* __restrict__ Bg,
    const float* __restrict__ bias, float* __restrict__ Cg)
{
    extern __shared__ float sm[];
    float* sA[2] = { sm,            sm + 4608  };
    float* sB[2] = { sm + 9216,     sm + 13824 };
    const uint32_t smb = smem_u32(sm);

    const int tid  = threadIdx.x;
    const int wid  = tid >> 5;
    const int lane = tid & 31;
    const int g    = lane >> 2;            // fragment group id
    const int fi   = lane & 3;             // thread-in-group
    const int wm   = (wid & 3) * 32;       // warp M offset
    const int wn   = (wid >> 2) * 64;      // warp N offset
    const int i0   = blockIdx.y * 128;
    const int j0   = blockIdx.x * 128;

    const int q     = tid & 7;             // float4 column within 32-float row
    const int rbase = tid >> 3;            // 0..31

    const float* ag = Ag + (size_t)(i0 + rbase) * 1024 + q * 4;
    const float* bg = Bg + (size_t)(j0 + rbase) * 1024 + q * 4;
    const uint32_t soff = (uint32_t)((rbase * SROW + q * 4) << 2);

    // stage loader: k-chunk s into buffer bf
    auto load_stage = [&](int s, int bf) {
        const int k0 = s * 32;
        const uint32_t sa = smb + (uint32_t)(((sA[bf] - sm)) << 2) + soff;
        const uint32_t sbx = smb + (uint32_t)(((sB[bf] - sm)) << 2) + soff;
        #pragma unroll
        for (int it = 0; it < 4; ++it) {
            cp_async16(sa  + it * (32 * SROW * 4), ag + (size_t)it * 32 * 1024 + k0);
            cp_async16(sbx + it * (32 * SROW * 4), bg + (size_t)it * 32 * 1024 + k0);
        }
    };

    float c[2][8][4];
    #pragma unroll
    for (int mt = 0; mt < 2; ++mt)
        #pragma unroll
        for (int nt = 0; nt < 8; ++nt)
            #pragma unroll
            for (int r = 0; r < 4; ++r) c[mt][nt][r] = 0.f;

    load_stage(0, 0); CP_COMMIT();
    load_stage(1, 1); CP_COMMIT();

    #pragma unroll 1
    for (int s = 0; s < 32; ++s) {
        const int bf = s & 1;
        CP_WAIT1();
        __syncthreads();
        const float* A = sA[bf];
        const float* B = sB[bf];
        #pragma unroll
        for (int kk = 0; kk < 4; ++kk) {
            const int k0 = kk * 8;
            uint32_t a[2][4];
            #pragma unroll
            for (int mt = 0; mt < 2; ++mt) {
                const int r = wm + mt * 16;
                a[mt][0] = f2tf(A[(r + g    ) * SROW + k0 + fi    ]);
                a[mt][1] = f2tf(A[(r + g + 8) * SROW + k0 + fi    ]);
                a[mt][2] = f2tf(A[(r + g    ) * SROW + k0 + fi + 4]);
                a[mt][3] = f2tf(A[(r + g + 8) * SROW + k0 + fi + 4]);
            }
            #pragma unroll
            for (int nt = 0; nt < 8; ++nt) {
                const int n = wn + nt * 8;
                uint32_t b0 = f2tf(B[(n + g) * SROW + k0 + fi    ]);
                uint32_t b1 = f2tf(B[(n + g) * SROW + k0 + fi + 4]);
                mma_tf32(c[0][nt], a[0][0], a[0][1], a[0][2], a[0][3], b0, b1);
                mma_tf32(c[1][nt], a[1][0], a[1][1], a[1][2], a[1][3], b0, b1);
            }
        }
        __syncthreads();
        if (s + 2 < 32) load_stage(s + 2, bf);
        CP_COMMIT();
    }

    // ---------- epilogue: stage C in smem, then coalesced global writes ----
    float* Cs = sm;                         // 128 x 136 floats = 69632 B
    __syncthreads();
    #pragma unroll
    for (int mt = 0; mt < 2; ++mt) {
        #pragma unroll
        for (int nt = 0; nt < 8; ++nt) {
            const int r  = wm + mt * 16 + g;
            const int cc = wn + nt * 8 + 2 * fi;
            *reinterpret_cast<float2*>(&Cs[(size_t)r * 136 + cc]) =
                make_float2(c[mt][nt][0], c[mt][nt][1]);
            *reinterpret_cast<float2*>(&Cs[(size_t)(r + 8) * 136 + cc]) =
                make_float2(c[mt][nt][2], c[mt][nt][3]);
        }
    }
    __syncthreads();

    #pragma unroll 1
    for (int p = 0; p < 16; ++p) {
        const int idx = p * 256 + tid;
        const int row = idx >> 5;           // 0..127  (i)
        const int qq  = idx & 31;           // float4 within row (j)
        float4 v = *reinterpret_cast<const float4*>(&Cs[(size_t)row * 136 + qq * 4]);
        if (MODE == 0) {
            const float be = __ldg(bias + i0 + row);
            v.x += be; v.y += be; v.z += be; v.w += be;
            const size_t base = ((size_t)(j0 >> 12) << 22) +
                                (size_t)(i0 + row) * 4096 + (j0 & 4095);
            *reinterpret_cast<float4*>(Cg + base + qq * 4) = v;
        } else {
            float4 bz = *reinterpret_cast<const float4*>(bias + j0 + qq * 4);
            v.x += bz.x; v.y += bz.y; v.z += bz.z; v.w += bz.w;
            *reinterpret_cast<float4*>(Cg + (size_t)(i0 + row) * 1024 + j0 + qq * 4) = v;
        }
    }
}

// ---------------- transpose: in [R, C] -> out [C, R], per-z batch -----------
__global__ void transpose_k(const float* __restrict__ in, float* __restrict__ out,
                            int R, int C) {
    __shared__ float t[32][33];
    const size_t base = (size_t)blockIdx.z * (size_t)R * C;
    const int r0 = blockIdx.y * 32;
    const int c0 = blockIdx.x * 32;
    #pragma unroll
    for (int i = threadIdx.y; i < 32; i += 8)
        t[i][threadIdx.x] = in[base + (size_t)(r0 + i) * C + c0 + threadIdx.x];
    __syncthreads();
    #pragma unroll
    for (int i = threadIdx.y; i < 32; i += 8)
        out[base + (size_t)(c0 + i) * R + r0 + threadIdx.x] = t[threadIdx.x][i];
}

// ======================= FFT conv path (fp32) ===============================
__device__ __forceinline__ float2 cadd(float2 a, float2 b) { return make_float2(a.x + b.x, a.y + b.y); }
__device__ __forceinline__ float2 csub(float2 a, float2 b) { return make_float2(a.x - b.x, a.y - b.y); }
__device__ __forceinline__ float2 cmul(float2 a, float2 b) {
    return make_float2(fmaf(a.x, b.x, -a.y * b.y), fmaf(a.x, b.y, a.y * b.x));
}

__device__ float2* fft8192(float2* x, float2* y, const float2* __restrict__ tw, int tid) {
    #pragma unroll 1
    for (int st = 0; st < 6; ++st) {
        const int sh = 2 * st;
        const int s  = 1 << sh;
        #pragma unroll
        for (int r = 0; r < 4; ++r) {
            const int i  = tid + r * 512;
            const int ps = i & ~(s - 1);
            float2 a = x[i];
            float2 b = x[i + 2048];
            float2 c = x[i + 4096];
            float2 d = x[i + 6144];
            float2 apc = cadd(a, c), amc = csub(a, c);
            float2 bpd = cadd(b, d), bmd = csub(b, d);
            float2 w1 = tw[ps];
            float2 w2 = cmul(w1, w1);
            float2 w3 = cmul(w1, w2);
            const int o = i + 3 * ps;
            y[o]         = cadd(apc, bpd);
            y[o + s]     = cmul(w1, make_float2(amc.x + bmd.y, amc.y - bmd.x));
            y[o + 2 * s] = cmul(w2, csub(apc, bpd));
            y[o + 3 * s] = cmul(w3, make_float2(amc.x - bmd.y, amc.y + bmd.x));
        }
        __syncthreads();
        float2* t = x; x = y; y = t;
    }
    #pragma unroll
    for (int r = 0; r < 8; ++r) {
        const int i = tid + r * 512;
        float2 a = x[i], b = x[i + 4096];
        y[i]        = cadd(a, b);
        y[i + 4096] = csub(a, b);
    }
    __syncthreads();
    return y;
}

__global__ void twiddle_kernel(float2* __restrict__ tw) {
    int k = blockIdx.x * blockDim.x + threadIdx.x;
    if (k < 2048) {
        float s, c;
        sincospif((float)k / 4096.0f, &s, &c);
        tw[k] = make_float2(c, -s);
    }
}

__global__ void filter_kernel(const float* __restrict__ hfilt,
                              const float2* __restrict__ gtw,
                              float2* __restrict__ Hf) {
    extern __shared__ float2 smf[];
    float2* buf0 = smf;
    float2* buf1 = smf + 8192;
    float2* tw   = smf + 16384;
    const int tid = threadIdx.x;
    const int d   = blockIdx.x;
    for (int k = tid; k < 2048; k += 512) tw[k] = gtw[k];
    for (int l = tid; l < 4096; l += 512) {
        float h = hfilt[(size_t)l * D_DIM + d] * expf(-0.01f * (float)l);
        buf0[l]        = make_float2(h, 0.f);
        buf0[l + 4096] = make_float2(0.f, 0.f);
    }
    __syncthreads();
    float2* R = fft8192(buf0, buf1, tw, tid);
    float2* out = Hf + (size_t)d * NFFT;
    for (int k = tid; k < NFFT; k += 512) out[k] = R[k];
}

__global__ void conv_kernel(const float* __restrict__ vT,
                            const float* __restrict__ uT,
                            const float2* __restrict__ Hf,
                            const float2* __restrict__ gtw,
                            float* __restrict__ yT) {
    extern __shared__ float2 smf[];
    float2* buf0 = smf;
    float2* buf1 = smf + 8192;
    float2* tw   = smf + 16384;
    const int tid = threadIdx.x;
    const int ch  = blockIdx.x;
    const int d   = ch & (D_DIM - 1);

    const float* vch = vT + (size_t)ch * L_DIM;
    for (int k = tid; k < 2048; k += 512) tw[k] = gtw[k];
    for (int l = tid; l < 4096; l += 512) {
        buf0[l]        = make_float2(vch[l], 0.f);
        buf0[l + 4096] = make_float2(0.f, 0.f);
    }
    __syncthreads();

    float2* V = fft8192(buf0, buf1, tw, tid);

    const float2* Hd = Hf + (size_t)d * NFFT;
    for (int k = tid; k < NFFT; k += 512) {
        float2 z = cmul(V[k], Hd[k]);
        buf0[k] = make_float2(z.x, -z.y);
    }
    __syncthreads();

    float2* R = fft8192(buf0, buf1, tw, tid);

    const float* uch = uT + (size_t)ch * L_DIM;
    float*       ych = yT + (size_t)ch * L_DIM;
    const float inv = 1.0f / (float)NFFT;
    for (int l = tid; l < 4096; l += 512)
        ych[l] = R[l].x * inv * uch[l];
}

// ======================= launch =============================================
extern "C" void kernel_launch(void* const* d_in, const int* in_sizes, int n_in,
                              void* d_out, int out_size) {
    const float* x   = (const float*)d_in[0];
    const float* Wu  = (const float*)d_in[1];
    const float* bu  = (const float*)d_in[2];
    const float* Wv  = (const float*)d_in[3];
    const float* bv  = (const float*)d_in[4];
    const float* hfl = (const float*)d_in[5];
    const float* Wo  = (const float*)d_in[6];
    const float* bo  = (const float*)d_in[7];
    float* out = (float*)d_out;

    void *pU, *pV, *pW, *pH, *pT;
    cudaGetSymbolAddress(&pU, g_uT);
    cudaGetSymbolAddress(&pV, g_vT);
    cudaGetSymbolAddress(&pW, g_Wt);
    cudaGetSymbolAddress(&pH, g_Hf);
    cudaGetSymbolAddress(&pT, g_tw);
    float* Wt = (float*)pW;

    const int SMEM_FFT = (16384 + 2048) * (int)sizeof(float2);  // 147456 B
    cudaFuncSetAttribute(filter_kernel, cudaFuncAttributeMaxDynamicSharedMemorySize, SMEM_FFT);
    cudaFuncSetAttribute(conv_kernel,   cudaFuncAttributeMaxDynamicSharedMemorySize, SMEM_FFT);
    cudaFuncSetAttribute(gemm_mma<0>, cudaFuncAttributeMaxDynamicSharedMemorySize, GEMM_SMEM_BYTES);
    cudaFuncSetAttribute(gemm_mma<1>, cudaFuncAttributeMaxDynamicSharedMemorySize, GEMM_SMEM_BYTES);

    twiddle_kernel<<<8, 256>>>((float2*)pT);

    // Weight transposes: W[d][e] -> Wt[e][d]  (K-major operands for MMA)
    dim3 tb(32, 8);
    transpose_k<<<dim3(32, 32, 1), tb>>>(Wu, Wt,                   1024, 1024);
    transpose_k<<<dim3(32, 32, 1), tb>>>(Wv, Wt + 1024 * 1024,     1024, 1024);
    transpose_k<<<dim3(32, 32, 1), tb>>>(Wo, Wt + 2 * 1024 * 1024, 1024, 1024);

    filter_kernel<<<D_DIM, 512, SMEM_FFT>>>(hfl, (const float2*)pT, (float2*)pH);

    // GEMM1: uT/vT[b,e,l]  (i = e rows from Wt, j = m rows from x)
    gemm_mma<0><<<dim3(128, 8), 256, GEMM_SMEM_BYTES>>>(Wt,               x, bu, (float*)pU);
    gemm_mma<0><<<dim3(128, 8), 256, GEMM_SMEM_BYTES>>>(Wt + 1024 * 1024, x, bv, (float*)pV);

    // conv: g_vT (v) -> g_vT (yT), gated by g_uT (u)
    conv_kernel<<<B_DIM * D_DIM, 512, SMEM_FFT>>>(
        (const float*)pV, (const float*)pU, (const float2*)pH, (const float2*)pT, (float*)pV);

    // yT[b,d,l] -> y[b,l,d] (into g_uT; u already consumed)
    transpose_k<<<dim3(128, 32, 4), tb>>>((const float*)pV, (float*)pU, 1024, 4096);

    // GEMM2: out[m,e] = y Wo + bo  (i = m rows from y, j = e rows from Wo^T)
    gemm_mma<1><<<dim3(8, 128), 256, GEMM_SMEM_BYTES>>>(
        (const float*)pU, Wt + 2 * 1024 * 1024, bo, out);
}

// round 4
// speedup vs baseline: 2.8472x; 1.3414x over previous
#include <cuda_runtime.h>
#include <math.h>
#include <cstdint>

#define B_DIM 4
#define L_DIM 4096
#define D_DIM 1024
#define NFFT 8192

// ---------------- scratch (static device globals; no allocation) -----------
__device__ float  g_uT[(size_t)B_DIM * D_DIM * L_DIM];   // [B, D, L] (later reused as y[B,L,D])
__device__ float  g_vT[(size_t)B_DIM * D_DIM * L_DIM];   // [B, D, L] (reused for yT)
__device__ float  g_Wt[(size_t)3 * D_DIM * D_DIM];       // Wu^T, Wv^T, Wo^T
__device__ float2 g_Hf[(size_t)D_DIM * NFFT];            // [D][k<=4096] used
__device__ float2 g_tw[2048];                            // exp(-2pi i k / 8192)

// ======================= portable PTX helpers ===============================
__device__ __forceinline__ uint32_t smem_u32(const void* p) {
    uint32_t a;
    asm("{ .reg .u64 t; cvta.to.shared.u64 t, %1; cvt.u32.u64 %0, t; }" : "=r"(a) : "l"(p));
    return a;
}
__device__ __forceinline__ uint32_t f2tf(float f) {
    uint32_t u; asm("cvt.rna.tf32.f32 %0, %1;" : "=r"(u) : "f"(f)); return u;
}
__device__ __forceinline__ void cp_async16(uint32_t saddr, const void* g) {
    asm volatile("cp.async.cg.shared.global [%0], [%1], 16;" :: "r"(saddr), "l"(g));
}
#define CP_COMMIT() asm volatile("cp.async.commit_group;" ::: "memory")
#define CP_WAIT1()  asm volatile("cp.async.wait_group 1;" ::: "memory")

__device__ __forceinline__ void mma_tf32(float* c,
    uint32_t a0, uint32_t a1, uint32_t a2, uint32_t a3, uint32_t b0, uint32_t b1) {
    asm volatile(
        "mma.sync.aligned.m16n8k8.row.col.f32.tf32.tf32.f32 "
        "{%0,%1,%2,%3}, {%4,%5,%6,%7}, {%8,%9}, {%0,%1,%2,%3};"
        : "+f"(c[0]), "+f"(c[1]), "+f"(c[2]), "+f"(c[3])
        : "r"(a0), "r"(a1), "r"(a2), "r"(a3), "r"(b0), "r"(b1));
}

// ======================= tf32 mma.sync GEMM =================================
// C[i][j] = sum_k A[i0+i][k] * B[j0+j][k]    A,B K-major (ld = 1024), K = 1024
// Tile 128x128x32, 8 warps (4 x 2), warp tile 32(M) x 64(N).
// MODE 0: i = e (A = W^T), j = m (B = x). out: outT[b][e][l] + bias[e(row)]
// MODE 1: i = m (A = y),  j = e (B = Wo^T). out: out[m][e] + bias[e(col)]
#define SROW 36
#define GEMM_SMEM_BYTES 73728

template <int MODE>
__global__ void __launch_bounds__(256, 2) gemm_mma(
    const float* __restrict__ Ag, const float* __restrict__ Bg,
    const float* __restrict__ bias, float* __restrict__ Cg)
{
    extern __shared__ float sm[];
    float* sA[2] = { sm,            sm + 4608  };
    float* sB[2] = { sm + 9216,     sm + 13824 };
    const uint32_t smb = smem_u32(sm);

    const int tid  = threadIdx.x;
    const int wid  = tid >> 5;
    const int lane = tid & 31;
    const int g    = lane >> 2;
    const int fi   = lane & 3;
    const int wm   = (wid & 3) * 32;
    const int wn   = (wid >> 2) * 64;
    const int i0   = blockIdx.y * 128;
    const int j0   = blockIdx.x * 128;

    const int q     = tid & 7;
    const int rbase = tid >> 3;

    const float* ag = Ag + (size_t)(i0 + rbase) * 1024 + q * 4;
    const float* bg = Bg + (size_t)(j0 + rbase) * 1024 + q * 4;
    const uint32_t soff = (uint32_t)((rbase * SROW + q * 4) << 2);

    auto load_stage = [&](int s, int bf) {
        const int k0 = s * 32;
        const uint32_t sa  = smb + (uint32_t)(((sA[bf] - sm)) << 2) + soff;
        const uint32_t sbx = smb + (uint32_t)(((sB[bf] - sm)) << 2) + soff;
        #pragma unroll
        for (int it = 0; it < 4; ++it) {
            cp_async16(sa  + it * (32 * SROW * 4), ag + (size_t)it * 32 * 1024 + k0);
            cp_async16(sbx + it * (32 * SROW * 4), bg + (size_t)it * 32 * 1024 + k0);
        }
    };

    float c[2][8][4];
    #pragma unroll
    for (int mt = 0; mt < 2; ++mt)
        #pragma unroll
        for (int nt = 0; nt < 8; ++nt)
            #pragma unroll
            for (int r = 0; r < 4; ++r) c[mt][nt][r] = 0.f;

    load_stage(0, 0); CP_COMMIT();
    load_stage(1, 1); CP_COMMIT();

    #pragma unroll 1
    for (int s = 0; s < 32; ++s) {
        const int bf = s & 1;
        CP_WAIT1();
        __syncthreads();
        const float* A = sA[bf];
        const float* B = sB[bf];
        #pragma unroll
        for (int kk = 0; kk < 4; ++kk) {
            const int k0 = kk * 8;
            uint32_t a[2][4];
            #pragma unroll
            for (int mt = 0; mt < 2; ++mt) {
                const int r = wm + mt * 16;
                a[mt][0] = f2tf(A[(r + g    ) * SROW + k0 + fi    ]);
                a[mt][1] = f2tf(A[(r + g + 8) * SROW + k0 + fi    ]);
                a[mt][2] = f2tf(A[(r + g    ) * SROW + k0 + fi + 4]);
                a[mt][3] = f2tf(A[(r + g + 8) * SROW + k0 + fi + 4]);
            }
            #pragma unroll
            for (int nt = 0; nt < 8; ++nt) {
                const int n = wn + nt * 8;
                uint32_t b0 = f2tf(B[(n + g) * SROW + k0 + fi    ]);
                uint32_t b1 = f2tf(B[(n + g) * SROW + k0 + fi + 4]);
                mma_tf32(c[0][nt], a[0][0], a[0][1], a[0][2], a[0][3], b0, b1);
                mma_tf32(c[1][nt], a[1][0], a[1][1], a[1][2], a[1][3], b0, b1);
            }
        }
        __syncthreads();
        if (s + 2 < 32) load_stage(s + 2, bf);
        CP_COMMIT();
    }

    float* Cs = sm;
    __syncthreads();
    #pragma unroll
    for (int mt = 0; mt < 2; ++mt) {
        #pragma unroll
        for (int nt = 0; nt < 8; ++nt) {
            const int r  = wm + mt * 16 + g;
            const int cc = wn + nt * 8 + 2 * fi;
            *reinterpret_cast<float2*>(&Cs[(size_t)r * 136 + cc]) =
                make_float2(c[mt][nt][0], c[mt][nt][1]);
            *reinterpret_cast<float2*>(&Cs[(size_t)(r + 8) * 136 + cc]) =
                make_float2(c[mt][nt][2], c[mt][nt][3]);
        }
    }
    __syncthreads();

    #pragma unroll 1
    for (int p = 0; p < 16; ++p) {
        const int idx = p * 256 + tid;
        const int row = idx >> 5;
        const int qq  = idx & 31;
        float4 v = *reinterpret_cast<const float4*>(&Cs[(size_t)row * 136 + qq * 4]);
        if (MODE == 0) {
            const float be = __ldg(bias + i0 + row);
            v.x += be; v.y += be; v.z += be; v.w += be;
            const size_t base = ((size_t)(j0 >> 12) << 22) +
                                (size_t)(i0 + row) * 4096 + (j0 & 4095);
            *reinterpret_cast<float4*>(Cg + base + qq * 4) = v;
        } else {
            float4 bz = *reinterpret_cast<const float4*>(bias + j0 + qq * 4);
            v.x += bz.x; v.y += bz.y; v.z += bz.z; v.w += bz.w;
            *reinterpret_cast<float4*>(Cg + (size_t)(i0 + row) * 1024 + j0 + qq * 4) = v;
        }
    }
}

// ---------------- transpose: in [R, C] -> out [C, R], per-z batch -----------
__global__ void transpose_k(const float* __restrict__ in, float* __restrict__ out,
                            int R, int C) {
    __shared__ float t[32][33];
    const size_t base = (size_t)blockIdx.z * (size_t)R * C;
    const int r0 = blockIdx.y * 32;
    const int c0 = blockIdx.x * 32;
    #pragma unroll
    for (int i = threadIdx.y; i < 32; i += 8)
        t[i][threadIdx.x] = in[base + (size_t)(r0 + i) * C + c0 + threadIdx.x];
    __syncthreads();
    #pragma unroll
    for (int i = threadIdx.y; i < 32; i += 8)
        out[base + (size_t)(c0 + i) * R + r0 + threadIdx.x] = t[threadIdx.x][i];
}

// ======================= FFT conv path (fp32) ===============================
__device__ __forceinline__ float2 cadd(float2 a, float2 b) { return make_float2(a.x + b.x, a.y + b.y); }
__device__ __forceinline__ float2 csub(float2 a, float2 b) { return make_float2(a.x - b.x, a.y - b.y); }
__device__ __forceinline__ float2 cmul(float2 a, float2 b) {
    return make_float2(fmaf(a.x, b.x, -a.y * b.y), fmaf(a.x, b.y, a.y * b.x));
}

__device__ float2* fft8192(float2* x, float2* y, const float2* __restrict__ tw, int tid) {
    #pragma unroll 1
    for (int st = 0; st < 6; ++st) {
        const int sh = 2 * st;
        const int s  = 1 << sh;
        #pragma unroll
        for (int r = 0; r < 4; ++r) {
            const int i  = tid + r * 512;
            const int ps = i & ~(s - 1);
            float2 a = x[i];
            float2 b = x[i + 2048];
            float2 c = x[i + 4096];
            float2 d = x[i + 6144];
            float2 apc = cadd(a, c), amc = csub(a, c);
            float2 bpd = cadd(b, d), bmd = csub(b, d);
            float2 w1 = tw[ps];
            float2 w2 = cmul(w1, w1);
            float2 w3 = cmul(w1, w2);
            const int o = i + 3 * ps;
            y[o]         = cadd(apc, bpd);
            y[o + s]     = cmul(w1, make_float2(amc.x + bmd.y, amc.y - bmd.x));
            y[o + 2 * s] = cmul(w2, csub(apc, bpd));
            y[o + 3 * s] = cmul(w3, make_float2(amc.x - bmd.y, amc.y + bmd.x));
        }
        __syncthreads();
        float2* t = x; x = y; y = t;
    }
    #pragma unroll
    for (int r = 0; r < 8; ++r) {
        const int i = tid + r * 512;
        float2 a = x[i], b = x[i + 4096];
        y[i]        = cadd(a, b);
        y[i + 4096] = csub(a, b);
    }
    __syncthreads();
    return y;
}

__global__ void twiddle_kernel(float2* __restrict__ tw) {
    int k = blockIdx.x * blockDim.x + threadIdx.x;
    if (k < 2048) {
        float s, c;
        sincospif((float)k / 4096.0f, &s, &c);
        tw[k] = make_float2(c, -s);
    }
}

// ---- packed filter FFT: 2 channels (d0 = 2*bid, d1 = d0+1) per block ------
// Stores Hermitian half: Hf[d][k] for k in [0, 4096].
__global__ void filter_kernel(const float* __restrict__ hfilt,
                              const float2* __restrict__ gtw,
                              float2* __restrict__ Hf) {
    extern __shared__ float2 smf[];
    float2* buf0 = smf;
    float2* buf1 = smf + 8192;
    float2* tw   = smf + 16384;
    const int tid = threadIdx.x;
    const int d0  = blockIdx.x * 2;

    for (int k = tid; k < 2048; k += 512) tw[k] = gtw[k];
    for (int l = tid; l < 4096; l += 512) {
        float dec = expf(-0.01f * (float)l);
        float2 h = *reinterpret_cast<const float2*>(hfilt + (size_t)l * D_DIM + d0);
        buf0[l]        = make_float2(h.x * dec, h.y * dec);
        buf0[l + 4096] = make_float2(0.f, 0.f);
    }
    __syncthreads();
    float2* Z = fft8192(buf0, buf1, tw, tid);

    float2* H0 = Hf + (size_t)d0 * NFFT;
    float2* H1 = H0 + NFFT;
    for (int k = tid; k <= 4096; k += 512) {
        const int km = (NFFT - k) & (NFFT - 1);
        float2 zk = Z[k], zm = Z[km];
        H0[k] = make_float2(0.5f * (zk.x + zm.x), 0.5f * (zk.y - zm.y));
        H1[k] = make_float2(0.5f * (zk.y + zm.y), 0.5f * (zm.x - zk.x));
    }
}

// ---- packed conv + gate: 2 channels per block ------------------------------
// Z = FFT(v0 + i v1); V0 = (Z(k)+conj(Z(-k)))/2, V1 = -i(Z(k)-conj(Z(-k)))/2
// Y = V0 H0 + i V1 H1 (Y(-k) from conjugate symmetry); y = ifft(Y) via conj trick.
__global__ void conv_kernel(const float* __restrict__ vT,
                            const float* __restrict__ uT,
                            const float2* __restrict__ Hf,
                            const float2* __restrict__ gtw,
                            float* __restrict__ yT) {
    extern __shared__ float2 smf[];
    float2* buf0 = smf;
    float2* buf1 = smf + 8192;
    float2* tw   = smf + 16384;
    const int tid = threadIdx.x;
    const int b   = blockIdx.x >> 9;
    const int d0  = (blockIdx.x & 511) * 2;
    const size_t row = ((size_t)b * D_DIM + d0) * L_DIM;

    const float* v0 = vT + row;
    const float* v1 = v0 + L_DIM;
    for (int k = tid; k < 2048; k += 512) tw[k] = gtw[k];
    for (int l = tid; l < 4096; l += 512) {
        buf0[l]        = make_float2(v0[l], v1[l]);
        buf0[l + 4096] = make_float2(0.f, 0.f);
    }
    __syncthreads();

    float2* Z = fft8192(buf0, buf1, tw, tid);       // Z in buf1

    const float2* H0 = Hf + (size_t)d0 * NFFT;
    const float2* H1 = H0 + NFFT;
    for (int k = tid; k <= 4096; k += 512) {
        const int km = (NFFT - k) & (NFFT - 1);
        float2 zk = Z[k], zm = Z[km];
        float2 vv0 = make_float2(0.5f * (zk.x + zm.x), 0.5f * (zk.y - zm.y));
        float2 vv1 = make_float2(0.5f * (zk.y + zm.y), 0.5f * (zm.x - zk.x));
        float2 P = cmul(vv0, __ldg(H0 + k));
        float2 Q = cmul(vv1, __ldg(H1 + k));
        // store conj(Y) for inverse-via-forward trick
        buf0[k]  = make_float2(P.x - Q.y, -(P.y + Q.x));   // conj(P + iQ)
        buf0[km] = make_float2(P.x + Q.y,  (P.y - Q.x));   // conj(conj(P) + i conj(Q))
    }
    __syncthreads();

    float2* R = fft8192(buf0, buf1, tw, tid);       // conj(R)/N = ifft(Y)

    const float* u0 = uT + row;
    const float* u1 = u0 + L_DIM;
    float* y0 = yT + row;
    float* y1 = y0 + L_DIM;
    const float inv = 1.0f / (float)NFFT;
    for (int l = tid; l < 4096; l += 512) {
        y0[l] =  R[l].x * inv * u0[l];
        y1[l] = -R[l].y * inv * u1[l];
    }
}

// ======================= launch =============================================
extern "C" void kernel_launch(void* const* d_in, const int* in_sizes, int n_in,
                              void* d_out, int out_size) {
    const float* x   = (const float*)d_in[0];
    const float* Wu  = (const float*)d_in[1];
    const float* bu  = (const float*)d_in[2];
    const float* Wv  = (const float*)d_in[3];
    const float* bv  = (const float*)d_in[4];
    const float* hfl = (const float*)d_in[5];
    const float* Wo  = (const float*)d_in[6];
    const float* bo  = (const float*)d_in[7];
    float* out = (float*)d_out;

    void *pU, *pV, *pW, *pH, *pT;
    cudaGetSymbolAddress(&pU, g_uT);
    cudaGetSymbolAddress(&pV, g_vT);
    cudaGetSymbolAddress(&pW, g_Wt);
    cudaGetSymbolAddress(&pH, g_Hf);
    cudaGetSymbolAddress(&pT, g_tw);
    float* Wt = (float*)pW;

    const int SMEM_FFT = (16384 + 2048) * (int)sizeof(float2);  // 147456 B
    cudaFuncSetAttribute(filter_kernel, cudaFuncAttributeMaxDynamicSharedMemorySize, SMEM_FFT);
    cudaFuncSetAttribute(conv_kernel,   cudaFuncAttributeMaxDynamicSharedMemorySize, SMEM_FFT);
    cudaFuncSetAttribute(gemm_mma<0>, cudaFuncAttributeMaxDynamicSharedMemorySize, GEMM_SMEM_BYTES);
    cudaFuncSetAttribute(gemm_mma<1>, cudaFuncAttributeMaxDynamicSharedMemorySize, GEMM_SMEM_BYTES);

    twiddle_kernel<<<8, 256>>>((float2*)pT);

    dim3 tb(32, 8);
    transpose_k<<<dim3(32, 32, 1), tb>>>(Wu, Wt,                   1024, 1024);
    transpose_k<<<dim3(32, 32, 1), tb>>>(Wv, Wt + 1024 * 1024,     1024, 1024);
    transpose_k<<<dim3(32, 32, 1), tb>>>(Wo, Wt + 2 * 1024 * 1024, 1024, 1024);

    filter_kernel<<<D_DIM / 2, 512, SMEM_FFT>>>(hfl, (const float2*)pT, (float2*)pH);

    // GEMM1: uT/vT[b,e,l]  (i = e rows from Wt, j = m rows from x)
    gemm_mma<0><<<dim3(128, 8), 256, GEMM_SMEM_BYTES>>>(Wt,               x, bu, (float*)pU);
    gemm_mma<0><<<dim3(128, 8), 256, GEMM_SMEM_BYTES>>>(Wt + 1024 * 1024, x, bv, (float*)pV);

    // packed conv: g_vT (v) -> g_vT (yT), gated by g_uT (u)
    conv_kernel<<<B_DIM * D_DIM / 2, 512, SMEM_FFT>>>(
        (const float*)pV, (const float*)pU, (const float2*)pH, (const float2*)pT, (float*)pV);

    // yT[b,d,l] -> y[b,l,d] (into g_uT; u already consumed)
    transpose_k<<<dim3(128, 32, 4), tb>>>((const float*)pV, (float*)pU, 1024, 4096);

    // GEMM2: out[m,e] = y Wo + bo
    gemm_mma<1><<<dim3(8, 128), 256, GEMM_SMEM_BYTES>>>(
        (const float*)pU, Wt + 2 * 1024 * 1024, bo, out);
}

// round 5
// speedup vs baseline: 3.2726x; 1.1494x over previous
#include <cuda_runtime.h>
#include <math.h>
#include <cstdint>

#define B_DIM 4
#define L_DIM 4096
#define D_DIM 1024
#define NFFT 8192

// ---------------- scratch (static device globals; no allocation) -----------
__device__ float  g_uT[(size_t)B_DIM * D_DIM * L_DIM];   // [B, D, L]
__device__ float  g_vT[(size_t)B_DIM * D_DIM * L_DIM];   // [B, D, L] (reused for yT)
__device__ float  g_xr[(size_t)B_DIM * L_DIM * D_DIM];   // x rounded to tf32
__device__ float  g_Wt[(size_t)3 * D_DIM * D_DIM];       // Wu^T, Wv^T, Wo^T (tf32-rounded)
__device__ float2 g_Hf[(size_t)D_DIM * NFFT];            // [D][k<=4096] used
__device__ float2 g_tw[NFFT];                            // exp(-2pi i k / 8192)

// ======================= portable PTX helpers ===============================
__device__ __forceinline__ uint32_t smem_u32(const void* p) {
    uint32_t a;
    asm("{ .reg .u64 t; cvta.to.shared.u64 t, %1; cvt.u32.u64 %0, t; }" : "=r"(a) : "l"(p));
    return a;
}
__device__ __forceinline__ uint32_t f2tf(float f) {
    uint32_t u; asm("cvt.rna.tf32.f32 %0, %1;" : "=r"(u) : "f"(f)); return u;
}
__device__ __forceinline__ void cp_async16(uint32_t saddr, const void* g) {
    asm volatile("cp.async.cg.shared.global [%0], [%1], 16;" :: "r"(saddr), "l"(g));
}
#define CP_COMMIT() asm volatile("cp.async.commit_group;" ::: "memory")
#define CP_WAIT1()  asm volatile("cp.async.wait_group 1;" ::: "memory")

__device__ __forceinline__ void mma_tf32(float* c,
    uint32_t a0, uint32_t a1, uint32_t a2, uint32_t a3, uint32_t b0, uint32_t b1) {
    asm volatile(
        "mma.sync.aligned.m16n8k8.row.col.f32.tf32.tf32.f32 "
        "{%0,%1,%2,%3}, {%4,%5,%6,%7}, {%8,%9}, {%0,%1,%2,%3};"
        : "+f"(c[0]), "+f"(c[1]), "+f"(c[2]), "+f"(c[3])
        : "r"(a0), "r"(a1), "r"(a2), "r"(a3), "r"(b0), "r"(b1));
}
__device__ __forceinline__ uint32_t u32f(float f) { return __float_as_uint(f); }

// ======================= tf32 mma.sync GEMM =================================
// MODE 0: A rows K-major (ld 1024), B rows K-major. C[i][j], i=e, j=m.
//         out: outT[b][e][l] + bias[row e]
// MODE 1: A = yT (tile loaded transposed: As2[k][i]), B rows K-major (Wo^T).
//         C[i][j], i=m, j=e. out: out[m][e] + bias[col e]
#define SROW 36
#define AROW2 136
#define GEMM_SMEM_BYTES 73728

template <int MODE>
__global__ void __launch_bounds__(256, 2) gemm_mma(
    const float* __restrict__ Ag, const float* __restrict__ Bg,
    const float* __restrict__ bias, float* __restrict__ Cg)
{
    extern __shared__ float sm[];
    // MODE 0: A buffers 128x36; MODE 1: A buffers 32x136 (transposed tile)
    const int ASZ = (MODE == 0) ? 4608 : 4352;
    float* sA[2] = { sm,            sm + ASZ   };
    float* sB[2] = { sm + 2 * ASZ,  sm + 2 * ASZ + 4608 };
    const uint32_t smb = smem_u32(sm);

    const int tid  = threadIdx.x;
    const int wid  = tid >> 5;
    const int lane = tid & 31;
    const int g    = lane >> 2;
    const int fi   = lane & 3;
    const int wm   = (wid & 3) * 32;
    const int wn   = (wid >> 2) * 64;
    const int i0   = blockIdx.y * 128;
    const int j0   = blockIdx.x * 128;

    const int q     = tid & 7;
    const int rbase = tid >> 3;

    // B stage source (both modes): rows j0.., K-major ld 1024
    const float* bg = Bg + (size_t)(j0 + rbase) * 1024 + q * 4;
    const uint32_t soffB = (uint32_t)((rbase * SROW + q * 4) << 2);

    // A stage source
    const float* ag;
    uint32_t soffA;
    int aq = 0, arow = 0;
    if (MODE == 0) {
        ag = Ag + (size_t)(i0 + rbase) * 1024 + q * 4;
        soffA = (uint32_t)((rbase * SROW + q * 4) << 2);
    } else {
        const int bb = i0 >> 12, l0 = i0 & 4095;
        arow = tid >> 5;            // 0..7
        aq   = tid & 31;            // float4 within 128-float row
        ag = Ag + ((size_t)bb * 1024) * 4096 + l0 + aq * 4;
        soffA = (uint32_t)((arow * AROW2 + aq * 4) << 2);
    }

    auto load_stage = [&](int s, int bf) {
        const int k0 = s * 32;
        const uint32_t sa  = smb + (uint32_t)((sA[bf] - sm) << 2) + soffA;
        const uint32_t sbx = smb + (uint32_t)((sB[bf] - sm) << 2) + soffB;
        if (MODE == 0) {
            #pragma unroll
            for (int it = 0; it < 4; ++it)
                cp_async16(sa + it * (32 * SROW * 4), ag + (size_t)it * 32 * 1024 + k0);
        } else {
            #pragma unroll
            for (int it = 0; it < 4; ++it)
                cp_async16(sa + it * (8 * AROW2 * 4),
                           ag + (size_t)(k0 + arow + it * 8) * 4096);
        }
        #pragma unroll
        for (int it = 0; it < 4; ++it)
            cp_async16(sbx + it * (32 * SROW * 4), bg + (size_t)it * 32 * 1024 + k0);
    };

    float c[2][8][4];
    #pragma unroll
    for (int mt = 0; mt < 2; ++mt)
        #pragma unroll
        for (int nt = 0; nt < 8; ++nt)
            #pragma unroll
            for (int r = 0; r < 4; ++r) c[mt][nt][r] = 0.f;

    load_stage(0, 0); CP_COMMIT();
    load_stage(1, 1); CP_COMMIT();

    #pragma unroll 1
    for (int s = 0; s < 32; ++s) {
        const int bf = s & 1;
        CP_WAIT1();
        __syncthreads();
        const float* A = sA[bf];
        const float* B = sB[bf];
        #pragma unroll
        for (int kk = 0; kk < 4; ++kk) {
            const int k0 = kk * 8;
            uint32_t a[2][4];
            #pragma unroll
            for (int mt = 0; mt < 2; ++mt) {
                const int r = wm + mt * 16;
                if (MODE == 0) {
                    a[mt][0] = u32f(A[(r + g    ) * SROW + k0 + fi    ]);
                    a[mt][1] = u32f(A[(r + g + 8) * SROW + k0 + fi    ]);
                    a[mt][2] = u32f(A[(r + g    ) * SROW + k0 + fi + 4]);
                    a[mt][3] = u32f(A[(r + g + 8) * SROW + k0 + fi + 4]);
                } else {
                    a[mt][0] = u32f(A[(k0 + fi    ) * AROW2 + r + g    ]);
                    a[mt][1] = u32f(A[(k0 + fi    ) * AROW2 + r + g + 8]);
                    a[mt][2] = u32f(A[(k0 + fi + 4) * AROW2 + r + g    ]);
                    a[mt][3] = u32f(A[(k0 + fi + 4) * AROW2 + r + g + 8]);
                }
            }
            #pragma unroll
            for (int nt = 0; nt < 8; ++nt) {
                const int n = wn + nt * 8;
                uint32_t b0 = u32f(B[(n + g) * SROW + k0 + fi    ]);
                uint32_t b1 = u32f(B[(n + g) * SROW + k0 + fi + 4]);
                mma_tf32(c[0][nt], a[0][0], a[0][1], a[0][2], a[0][3], b0, b1);
                mma_tf32(c[1][nt], a[1][0], a[1][1], a[1][2], a[1][3], b0, b1);
            }
        }
        __syncthreads();
        if (s + 2 < 32) load_stage(s + 2, bf);
        CP_COMMIT();
    }

    float* Cs = sm;
    __syncthreads();
    #pragma unroll
    for (int mt = 0; mt < 2; ++mt) {
        #pragma unroll
        for (int nt = 0; nt < 8; ++nt) {
            const int r  = wm + mt * 16 + g;
            const int cc = wn + nt * 8 + 2 * fi;
            *reinterpret_cast<float2*>(&Cs[(size_t)r * 136 + cc]) =
                make_float2(c[mt][nt][0], c[mt][nt][1]);
            *reinterpret_cast<float2*>(&Cs[(size_t)(r + 8) * 136 + cc]) =
                make_float2(c[mt][nt][2], c[mt][nt][3]);
        }
    }
    __syncthreads();

    #pragma unroll 1
    for (int p = 0; p < 16; ++p) {
        const int idx = p * 256 + tid;
        const int row = idx >> 5;
        const int qq  = idx & 31;
        float4 v = *reinterpret_cast<const float4*>(&Cs[(size_t)row * 136 + qq * 4]);
        if (MODE == 0) {
            const float be = __ldg(bias + i0 + row);
            v.x += be; v.y += be; v.z += be; v.w += be;
            const size_t base = ((size_t)(j0 >> 12) << 22) +
                                (size_t)(i0 + row) * 4096 + (j0 & 4095);
            *reinterpret_cast<float4*>(Cg + base + qq * 4) = v;
        } else {
            float4 bz = *reinterpret_cast<const float4*>(bias + j0 + qq * 4);
            v.x += bz.x; v.y += bz.y; v.z += bz.z; v.w += bz.w;
            *reinterpret_cast<float4*>(Cg + (size_t)(i0 + row) * 1024 + j0 + qq * 4) = v;
        }
    }
}

// ---------------- weight transpose + tf32 rounding ---------------------------
__global__ void transpose_k(const float* __restrict__ in, float* __restrict__ out,
                            int R, int C) {
    __shared__ float t[32][33];
    const size_t base = (size_t)blockIdx.z * (size_t)R * C;
    const int r0 = blockIdx.y * 32;
    const int c0 = blockIdx.x * 32;
    #pragma unroll
    for (int i = threadIdx.y; i < 32; i += 8)
        t[i][threadIdx.x] = in[base + (size_t)(r0 + i) * C + c0 + threadIdx.x];
    __syncthreads();
    #pragma unroll
    for (int i = threadIdx.y; i < 32; i += 8)
        out[base + (size_t)(c0 + i) * R + r0 + threadIdx.x] =
            __uint_as_float(f2tf(t[threadIdx.x][i]));
}

// ---------------- round x to tf32 -------------------------------------------
__global__ void round_tf32_k(const float* __restrict__ in, float* __restrict__ out) {
    const size_t i = ((size_t)blockIdx.x * 256 + threadIdx.x) * 4;
    float4 v = *reinterpret_cast<const float4*>(in + i);
    v.x = __uint_as_float(f2tf(v.x));
    v.y = __uint_as_float(f2tf(v.y));
    v.z = __uint_as_float(f2tf(v.z));
    v.w = __uint_as_float(f2tf(v.w));
    *reinterpret_cast<float4*>(out + i) = v;
}

// ======================= FFT conv path (fp32) ===============================
__device__ __forceinline__ float2 cadd(float2 a, float2 b) { return make_float2(a.x + b.x, a.y + b.y); }
__device__ __forceinline__ float2 csub(float2 a, float2 b) { return make_float2(a.x - b.x, a.y - b.y); }
__device__ __forceinline__ float2 cmul(float2 a, float2 b) {
    return make_float2(fmaf(a.x, b.x, -a.y * b.y), fmaf(a.x, b.y, a.y * b.x));
}

// 8192-pt forward FFT: 4 radix-8 Stockham stages + final radix-2.
// 1024 threads; tw = full 8192-entry table in smem. Result in returned buffer.
__device__ float2* fft8192_r8(float2* x, float2* y, const float2* __restrict__ tw, int tid) {
    const float RS2 = 0.70710678118654752f;
    #pragma unroll 1
    for (int st = 0; st < 4; ++st) {
        const int s  = 1 << (3 * st);           // 1, 8, 64, 512
        const int i  = tid;                     // one butterfly per thread
        const int ps = i & ~(s - 1);
        float2 x0 = x[i],        x1 = x[i + 1024], x2 = x[i + 2048], x3 = x[i + 3072];
        float2 x4 = x[i + 4096], x5 = x[i + 5120], x6 = x[i + 6144], x7 = x[i + 7168];
        float2 a0 = cadd(x0, x4), b0 = csub(x0, x4);
        float2 a1 = cadd(x1, x5), b1 = csub(x1, x5);
        float2 a2 = cadd(x2, x6), b2 = csub(x2, x6);
        float2 a3 = cadd(x3, x7), b3 = csub(x3, x7);
        // even outputs (q = 0,2,4,6): DFT4(a)
        float2 t0 = cadd(a0, a2), t1 = csub(a0, a2);
        float2 t2 = cadd(a1, a3), t3 = csub(a1, a3);
        float2 e0 = cadd(t0, t2);
        float2 e1 = make_float2(t1.x + t3.y, t1.y - t3.x);
        float2 e2 = csub(t0, t2);
        float2 e3 = make_float2(t1.x - t3.y, t1.y + t3.x);
        // odd outputs (q = 1,3,5,7): DFT4(b_r * w8^r)
        float2 c0 = b0;
        float2 c1 = make_float2((b1.x + b1.y) * RS2, (b1.y - b1.x) * RS2);
        float2 c2 = make_float2(b2.y, -b2.x);
        float2 c3 = make_float2((b3.y - b3.x) * RS2, -(b3.x + b3.y) * RS2);
        float2 u0 = cadd(c0, c2), u1 = csub(c0, c2);
        float2 u2 = cadd(c1, c3), u3 = csub(c1, c3);
        float2 o0 = cadd(u0, u2);
        float2 o1 = make_float2(u1.x + u3.y, u1.y - u3.x);
        float2 o2 = csub(u0, u2);
        float2 o3 = make_float2(u1.x - u3.y, u1.y + u3.x);
        const int o = i + 7 * ps;
        y[o]         = e0;
        y[o +     s] = cmul(tw[ps],     o0);
        y[o + 2 * s] = cmul(tw[2 * ps], e1);
        y[o + 3 * s] = cmul(tw[3 * ps], o1);
        y[o + 4 * s] = cmul(tw[4 * ps], e2);
        y[o + 5 * s] = cmul(tw[5 * ps], o2);
        y[o + 6 * s] = cmul(tw[6 * ps], e3);
        y[o + 7 * s] = cmul(tw[7 * ps], o3);
        __syncthreads();
        float2* t = x; x = y; y = t;
    }
    // final radix-2 (s = 4096, no twiddle)
    #pragma unroll
    for (int r = 0; r < 4; ++r) {
        const int i = tid + r * 1024;
        float2 a = x[i], b = x[i + 4096];
        y[i]        = cadd(a, b);
        y[i + 4096] = csub(a, b);
    }
    __syncthreads();
    return y;
}

__global__ void twiddle_kernel(float2* __restrict__ tw) {
    int k = blockIdx.x * blockDim.x + threadIdx.x;
    if (k < NFFT) {
        float s, c;
        sincospif((float)k / 4096.0f, &s, &c);
        tw[k] = make_float2(c, -s);
    }
}

#define SMEM_FFT ((16384 + 8192) * (int)sizeof(float2))   // 196608 B

// ---- packed filter FFT: 2 channels per block; stores Hermitian half --------
__global__ void __launch_bounds__(1024, 1) filter_kernel(
    const float* __restrict__ hfilt, const float2* __restrict__ gtw,
    float2* __restrict__ Hf) {
    extern __shared__ float2 smf[];
    float2* buf0 = smf;
    float2* buf1 = smf + 8192;
    float2* tw   = smf + 16384;
    const int tid = threadIdx.x;
    const int d0  = blockIdx.x * 2;

    for (int k = tid; k < NFFT; k += 1024) tw[k] = gtw[k];
    for (int l = tid; l < 4096; l += 1024) {
        float dec = expf(-0.01f * (float)l);
        float2 h = *reinterpret_cast<const float2*>(hfilt + (size_t)l * D_DIM + d0);
        buf0[l]        = make_float2(h.x * dec, h.y * dec);
        buf0[l + 4096] = make_float2(0.f, 0.f);
    }
    __syncthreads();
    float2* Z = fft8192_r8(buf0, buf1, tw, tid);

    float2* H0 = Hf + (size_t)d0 * NFFT;
    float2* H1 = H0 + NFFT;
    for (int k = tid; k <= 4096; k += 1024) {
        const int km = (NFFT - k) & (NFFT - 1);
        float2 zk = Z[k], zm = Z[km];
        H0[k] = make_float2(0.5f * (zk.x + zm.x), 0.5f * (zk.y - zm.y));
        H1[k] = make_float2(0.5f * (zk.y + zm.y), 0.5f * (zm.x - zk.x));
    }
}

// ---- packed conv + gate: 2 channels per block; output rounded to tf32 ------
__global__ void __launch_bounds__(1024, 1) conv_kernel(
    const float* __restrict__ vT, const float* __restrict__ uT,
    const float2* __restrict__ Hf, const float2* __restrict__ gtw,
    float* __restrict__ yT) {
    extern __shared__ float2 smf[];
    float2* buf0 = smf;
    float2* buf1 = smf + 8192;
    float2* tw   = smf + 16384;
    const int tid = threadIdx.x;
    const int b   = blockIdx.x >> 9;
    const int d0  = (blockIdx.x & 511) * 2;
    const size_t row = ((size_t)b * D_DIM + d0) * L_DIM;

    const float* v0 = vT + row;
    const float* v1 = v0 + L_DIM;
    for (int k = tid; k < NFFT; k += 1024) tw[k] = gtw[k];
    for (int l = tid; l < 4096; l += 1024) {
        buf0[l]        = make_float2(v0[l], v1[l]);
        buf0[l + 4096] = make_float2(0.f, 0.f);
    }
    __syncthreads();

    float2* Z = fft8192_r8(buf0, buf1, tw, tid);     // Z in buf1

    const float2* H0 = Hf + (size_t)d0 * NFFT;
    const float2* H1 = H0 + NFFT;
    for (int k = tid; k <= 4096; k += 1024) {
        const int km = (NFFT - k) & (NFFT - 1);
        float2 zk = Z[k], zm = Z[km];
        float2 vv0 = make_float2(0.5f * (zk.x + zm.x), 0.5f * (zk.y - zm.y));
        float2 vv1 = make_float2(0.5f * (zk.y + zm.y), 0.5f * (zm.x - zk.x));
        float2 P = cmul(vv0, __ldg(H0 + k));
        float2 Q = cmul(vv1, __ldg(H1 + k));
        buf0[k]  = make_float2(P.x - Q.y, -(P.y + Q.x));
        buf0[km] = make_float2(P.x + Q.y,  (P.y - Q.x));
    }
    __syncthreads();

    float2* R = fft8192_r8(buf0, buf1, tw, tid);     // conj(R)/N = ifft(Y)

    const float* u0 = uT + row;
    const float* u1 = u0 + L_DIM;
    float* y0 = yT + row;
    float* y1 = y0 + L_DIM;
    const float inv = 1.0f / (float)NFFT;
    for (int l = tid; l < 4096; l += 1024) {
        y0[l] = __uint_as_float(f2tf( R[l].x * inv * u0[l]));
        y1[l] = __uint_as_float(f2tf(-R[l].y * inv * u1[l]));
    }
}

// ======================= launch =============================================
extern "C" void kernel_launch(void* const* d_in, const int* in_sizes, int n_in,
                              void* d_out, int out_size) {
    const float* x   = (const float*)d_in[0];
    const float* Wu  = (const float*)d_in[1];
    const float* bu  = (const float*)d_in[2];
    const float* Wv  = (const float*)d_in[3];
    const float* bv  = (const float*)d_in[4];
    const float* hfl = (const float*)d_in[5];
    const float* Wo  = (const float*)d_in[6];
    const float* bo  = (const float*)d_in[7];
    float* out = (float*)d_out;

    void *pU, *pV, *pX, *pW, *pH, *pT;
    cudaGetSymbolAddress(&pU, g_uT);
    cudaGetSymbolAddress(&pV, g_vT);
    cudaGetSymbolAddress(&pX, g_xr);
    cudaGetSymbolAddress(&pW, g_Wt);
    cudaGetSymbolAddress(&pH, g_Hf);
    cudaGetSymbolAddress(&pT, g_tw);
    float* Wt = (float*)pW;

    cudaFuncSetAttribute(filter_kernel, cudaFuncAttributeMaxDynamicSharedMemorySize, SMEM_FFT);
    cudaFuncSetAttribute(conv_kernel,   cudaFuncAttributeMaxDynamicSharedMemorySize, SMEM_FFT);
    cudaFuncSetAttribute(gemm_mma<0>, cudaFuncAttributeMaxDynamicSharedMemorySize, GEMM_SMEM_BYTES);
    cudaFuncSetAttribute(gemm_mma<1>, cudaFuncAttributeMaxDynamicSharedMemorySize, GEMM_SMEM_BYTES);

    twiddle_kernel<<<32, 256>>>((float2*)pT);

    round_tf32_k<<<16384, 256>>>(x, (float*)pX);

    dim3 tb(32, 8);
    transpose_k<<<dim3(32, 32, 1), tb>>>(Wu, Wt,                   1024, 1024);
    transpose_k<<<dim3(32, 32, 1), tb>>>(Wv, Wt + 1024 * 1024,     1024, 1024);
    transpose_k<<<dim3(32, 32, 1), tb>>>(Wo, Wt + 2 * 1024 * 1024, 1024, 1024);

    filter_kernel<<<D_DIM / 2, 1024, SMEM_FFT>>>(hfl, (const float2*)pT, (float2*)pH);

    // GEMM1: uT/vT[b,e,l]  (i = e rows from Wt, j = m rows from rounded x)
    gemm_mma<0><<<dim3(128, 8), 256, GEMM_SMEM_BYTES>>>(Wt,               (const float*)pX, bu, (float*)pU);
    gemm_mma<0><<<dim3(128, 8), 256, GEMM_SMEM_BYTES>>>(Wt + 1024 * 1024, (const float*)pX, bv, (float*)pV);

    // packed conv: g_vT (v) -> g_vT (yT, tf32-rounded), gated by g_uT (u)
    conv_kernel<<<B_DIM * D_DIM / 2, 1024, SMEM_FFT>>>(
        (const float*)pV, (const float*)pU, (const float2*)pH, (const float2*)pT, (float*)pV);

    // GEMM2: out[m,e] = y Wo + bo  (A read transposed from yT — no copy)
    gemm_mma<1><<<dim3(8, 128), 256, GEMM_SMEM_BYTES>>>(
        (const float*)pV, Wt + 2 * 1024 * 1024, bo, out);
}

// round 6
// speedup vs baseline: 3.4265x; 1.0470x over previous
#include <cuda_runtime.h>
#include <math.h>
#include <cstdint>

#define B_DIM 4
#define L_DIM 4096
#define D_DIM 1024
#define NFFT 8192

// ---------------- scratch (static device globals; no allocation) -----------
__device__ float  g_uT[(size_t)B_DIM * D_DIM * L_DIM];   // [B, D, L]
__device__ float  g_vT[(size_t)B_DIM * D_DIM * L_DIM];   // [B, D, L] (reused for yT)
__device__ float  g_xr[(size_t)B_DIM * L_DIM * D_DIM];   // x rounded to tf32
__device__ float  g_Wt[(size_t)3 * D_DIM * D_DIM];       // Wu^T, Wv^T, Wo^T (tf32-rounded)
__device__ float2 g_Hf[(size_t)D_DIM * NFFT];            // [D][k<=4096] used
__device__ float2 g_tw[NFFT];                            // exp(-2pi i k / 8192)

// ======================= portable PTX helpers ===============================
__device__ __forceinline__ uint32_t smem_u32(const void* p) {
    uint32_t a;
    asm("{ .reg .u64 t; cvta.to.shared.u64 t, %1; cvt.u32.u64 %0, t; }" : "=r"(a) : "l"(p));
    return a;
}
__device__ __forceinline__ uint32_t f2tf(float f) {
    uint32_t u; asm("cvt.rna.tf32.f32 %0, %1;" : "=r"(u) : "f"(f)); return u;
}
__device__ __forceinline__ void cp_async16(uint32_t saddr, const void* g) {
    asm volatile("cp.async.cg.shared.global [%0], [%1], 16;" :: "r"(saddr), "l"(g));
}
#define CP_COMMIT() asm volatile("cp.async.commit_group;" ::: "memory")
#define CP_WAIT1()  asm volatile("cp.async.wait_group 1;" ::: "memory")

__device__ __forceinline__ void mma_tf32(float* c,
    uint32_t a0, uint32_t a1, uint32_t a2, uint32_t a3, uint32_t b0, uint32_t b1) {
    asm volatile(
        "mma.sync.aligned.m16n8k8.row.col.f32.tf32.tf32.f32 "
        "{%0,%1,%2,%3}, {%4,%5,%6,%7}, {%8,%9}, {%0,%1,%2,%3};"
        : "+f"(c[0]), "+f"(c[1]), "+f"(c[2]), "+f"(c[3])
        : "r"(a0), "r"(a1), "r"(a2), "r"(a3), "r"(b0), "r"(b1));
}
__device__ __forceinline__ uint32_t u32f(float f) { return __float_as_uint(f); }

// ======================= tf32 mma.sync GEMM (unchanged) =====================
#define SROW 36
#define AROW2 136
#define GEMM_SMEM_BYTES 73728

template <int MODE>
__global__ void __launch_bounds__(256, 2) gemm_mma(
    const float* __restrict__ Ag, const float* __restrict__ Bg,
    const float* __restrict__ bias, float* __restrict__ Cg)
{
    extern __shared__ float sm[];
    const int ASZ = (MODE == 0) ? 4608 : 4352;
    float* sA[2] = { sm,            sm + ASZ   };
    float* sB[2] = { sm + 2 * ASZ,  sm + 2 * ASZ + 4608 };
    const uint32_t smb = smem_u32(sm);

    const int tid  = threadIdx.x;
    const int lane = tid & 31;
    const int wid  = tid >> 5;
    const int g    = lane >> 2;
    const int fi   = lane & 3;
    const int wm   = (wid & 3) * 32;
    const int wn   = (wid >> 2) * 64;
    const int i0   = blockIdx.y * 128;
    const int j0   = blockIdx.x * 128;

    const int q     = tid & 7;
    const int rbase = tid >> 3;

    const float* bg = Bg + (size_t)(j0 + rbase) * 1024 + q * 4;
    const uint32_t soffB = (uint32_t)((rbase * SROW + q * 4) << 2);

    const float* ag;
    uint32_t soffA;
    int aq = 0, arow = 0;
    if (MODE == 0) {
        ag = Ag + (size_t)(i0 + rbase) * 1024 + q * 4;
        soffA = (uint32_t)((rbase * SROW + q * 4) << 2);
    } else {
        const int bb = i0 >> 12, l0 = i0 & 4095;
        arow = tid >> 5;
        aq   = tid & 31;
        ag = Ag + ((size_t)bb * 1024) * 4096 + l0 + aq * 4;
        soffA = (uint32_t)((arow * AROW2 + aq * 4) << 2);
    }

    auto load_stage = [&](int s, int bf) {
        const int k0 = s * 32;
        const uint32_t sa  = smb + (uint32_t)((sA[bf] - sm) << 2) + soffA;
        const uint32_t sbx = smb + (uint32_t)((sB[bf] - sm) << 2) + soffB;
        if (MODE == 0) {
            #pragma unroll
            for (int it = 0; it < 4; ++it)
                cp_async16(sa + it * (32 * SROW * 4), ag + (size_t)it * 32 * 1024 + k0);
        } else {
            #pragma unroll
            for (int it = 0; it < 4; ++it)
                cp_async16(sa + it * (8 * AROW2 * 4),
                           ag + (size_t)(k0 + arow + it * 8) * 4096);
        }
        #pragma unroll
        for (int it = 0; it < 4; ++it)
            cp_async16(sbx + it * (32 * SROW * 4), bg + (size_t)it * 32 * 1024 + k0);
    };

    float c[2][8][4];
    #pragma unroll
    for (int mt = 0; mt < 2; ++mt)
        #pragma unroll
        for (int nt = 0; nt < 8; ++nt)
            #pragma unroll
            for (int r = 0; r < 4; ++r) c[mt][nt][r] = 0.f;

    load_stage(0, 0); CP_COMMIT();
    load_stage(1, 1); CP_COMMIT();

    #pragma unroll 1
    for (int s = 0; s < 32; ++s) {
        const int bf = s & 1;
        CP_WAIT1();
        __syncthreads();
        const float* A = sA[bf];
        const float* B = sB[bf];
        #pragma unroll
        for (int kk = 0; kk < 4; ++kk) {
            const int k0 = kk * 8;
            uint32_t a[2][4];
            #pragma unroll
            for (int mt = 0; mt < 2; ++mt) {
                const int r = wm + mt * 16;
                if (MODE == 0) {
                    a[mt][0] = u32f(A[(r + g    ) * SROW + k0 + fi    ]);
                    a[mt][1] = u32f(A[(r + g + 8) * SROW + k0 + fi    ]);
                    a[mt][2] = u32f(A[(r + g    ) * SROW + k0 + fi + 4]);
                    a[mt][3] = u32f(A[(r + g + 8) * SROW + k0 + fi + 4]);
                } else {
                    a[mt][0] = u32f(A[(k0 + fi    ) * AROW2 + r + g    ]);
                    a[mt][1] = u32f(A[(k0 + fi    ) * AROW2 + r + g + 8]);
                    a[mt][2] = u32f(A[(k0 + fi + 4) * AROW2 + r + g    ]);
                    a[mt][3] = u32f(A[(k0 + fi + 4) * AROW2 + r + g + 8]);
                }
            }
            #pragma unroll
            for (int nt = 0; nt < 8; ++nt) {
                const int n = wn + nt * 8;
                uint32_t b0 = u32f(B[(n + g) * SROW + k0 + fi    ]);
                uint32_t b1 = u32f(B[(n + g) * SROW + k0 + fi + 4]);
                mma_tf32(c[0][nt], a[0][0], a[0][1], a[0][2], a[0][3], b0, b1);
                mma_tf32(c[1][nt], a[1][0], a[1][1], a[1][2], a[1][3], b0, b1);
            }
        }
        __syncthreads();
        if (s + 2 < 32) load_stage(s + 2, bf);
        CP_COMMIT();
    }

    float* Cs = sm;
    __syncthreads();
    #pragma unroll
    for (int mt = 0; mt < 2; ++mt) {
        #pragma unroll
        for (int nt = 0; nt < 8; ++nt) {
            const int r  = wm + mt * 16 + g;
            const int cc = wn + nt * 8 + 2 * fi;
            *reinterpret_cast<float2*>(&Cs[(size_t)r * 136 + cc]) =
                make_float2(c[mt][nt][0], c[mt][nt][1]);
            *reinterpret_cast<float2*>(&Cs[(size_t)(r + 8) * 136 + cc]) =
                make_float2(c[mt][nt][2], c[mt][nt][3]);
        }
    }
    __syncthreads();

    #pragma unroll 1
    for (int p = 0; p < 16; ++p) {
        const int idx = p * 256 + tid;
        const int row = idx >> 5;
        const int qq  = idx & 31;
        float4 v = *reinterpret_cast<const float4*>(&Cs[(size_t)row * 136 + qq * 4]);
        if (MODE == 0) {
            const float be = __ldg(bias + i0 + row);
            v.x += be; v.y += be; v.z += be; v.w += be;
            const size_t base = ((size_t)(j0 >> 12) << 22) +
                                (size_t)(i0 + row) * 4096 + (j0 & 4095);
            *reinterpret_cast<float4*>(Cg + base + qq * 4) = v;
        } else {
            float4 bz = *reinterpret_cast<const float4*>(bias + j0 + qq * 4);
            v.x += bz.x; v.y += bz.y; v.z += bz.z; v.w += bz.w;
            *reinterpret_cast<float4*>(Cg + (size_t)(i0 + row) * 1024 + j0 + qq * 4) = v;
        }
    }
}

// ---------------- weight transpose + tf32 rounding ---------------------------
__global__ void transpose_k(const float* __restrict__ in, float* __restrict__ out,
                            int R, int C) {
    __shared__ float t[32][33];
    const size_t base = (size_t)blockIdx.z * (size_t)R * C;
    const int r0 = blockIdx.y * 32;
    const int c0 = blockIdx.x * 32;
    #pragma unroll
    for (int i = threadIdx.y; i < 32; i += 8)
        t[i][threadIdx.x] = in[base + (size_t)(r0 + i) * C + c0 + threadIdx.x];
    __syncthreads();
    #pragma unroll
    for (int i = threadIdx.y; i < 32; i += 8)
        out[base + (size_t)(c0 + i) * R + r0 + threadIdx.x] =
            __uint_as_float(f2tf(t[threadIdx.x][i]));
}

__global__ void round_tf32_k(const float* __restrict__ in, float* __restrict__ out) {
    const size_t i = ((size_t)blockIdx.x * 256 + threadIdx.x) * 4;
    float4 v = *reinterpret_cast<const float4*>(in + i);
    v.x = __uint_as_float(f2tf(v.x));
    v.y = __uint_as_float(f2tf(v.y));
    v.z = __uint_as_float(f2tf(v.z));
    v.w = __uint_as_float(f2tf(v.w));
    *reinterpret_cast<float4*>(out + i) = v;
}

// ======================= FFT conv path (fp32) ===============================
__device__ __forceinline__ float2 cadd(float2 a, float2 b) { return make_float2(a.x + b.x, a.y + b.y); }
__device__ __forceinline__ float2 csub(float2 a, float2 b) { return make_float2(a.x - b.x, a.y - b.y); }
__device__ __forceinline__ float2 cmul(float2 a, float2 b) {
    return make_float2(fmaf(a.x, b.x, -a.y * b.y), fmaf(a.x, b.y, a.y * b.x));
}

// bank-conflict-avoiding buffer swizzle (bijective involution on [0, 8192))
#define SWZ(e) ((e) ^ (((e) >> 4) & 7))

// 8192-pt forward FFT: 4 radix-8 Stockham stages (+ optional final radix-2).
// PAD: input known zero in [4096, 8192) (skips those loads in stage 0).
// FINAL_R2: run the final radix-2; if false, caller combines pairs
//           R[l] = P[l] + P[l+4096] (and difference) itself.
// 1024 threads; tw = full 8192-entry table in smem (not swizzled).
template <bool PAD, bool FINAL_R2>
__device__ float2* fft8192_r8(float2* x, float2* y, const float2* __restrict__ tw, int tid) {
    const float RS2 = 0.70710678118654752f;
    #pragma unroll 1
    for (int st = 0; st < 4; ++st) {
        const int s  = 1 << (3 * st);           // 1, 8, 64, 512
        const int i  = tid;
        const int ps = i & ~(s - 1);
        float2 a0, a1, a2, a3, b0, b1, b2, b3;
        {
            float2 x0 = x[SWZ(i)],        x1 = x[SWZ(i + 1024)];
            float2 x2 = x[SWZ(i + 2048)], x3 = x[SWZ(i + 3072)];
            if (PAD && st == 0) {
                a0 = x0; b0 = x0; a1 = x1; b1 = x1;
                a2 = x2; b2 = x2; a3 = x3; b3 = x3;
            } else {
                float2 x4 = x[SWZ(i + 4096)], x5 = x[SWZ(i + 5120)];
                float2 x6 = x[SWZ(i + 6144)], x7 = x[SWZ(i + 7168)];
                a0 = cadd(x0, x4); b0 = csub(x0, x4);
                a1 = cadd(x1, x5); b1 = csub(x1, x5);
                a2 = cadd(x2, x6); b2 = csub(x2, x6);
                a3 = cadd(x3, x7); b3 = csub(x3, x7);
            }
        }
        // even outputs: DFT4(a)
        float2 t0 = cadd(a0, a2), t1 = csub(a0, a2);
        float2 t2 = cadd(a1, a3), t3 = csub(a1, a3);
        float2 e0 = cadd(t0, t2);
        float2 e1 = make_float2(t1.x + t3.y, t1.y - t3.x);
        float2 e2 = csub(t0, t2);
        float2 e3 = make_float2(t1.x - t3.y, t1.y + t3.x);
        // odd outputs: DFT4(b_r * w8^r)
        float2 c0 = b0;
        float2 c1 = make_float2((b1.x + b1.y) * RS2, (b1.y - b1.x) * RS2);
        float2 c2 = make_float2(b2.y, -b2.x);
        float2 c3 = make_float2((b3.y - b3.x) * RS2, -(b3.x + b3.y) * RS2);
        float2 u0 = cadd(c0, c2), u1 = csub(c0, c2);
        float2 u2 = cadd(c1, c3), u3 = csub(c1, c3);
        float2 o0 = cadd(u0, u2);
        float2 o1 = make_float2(u1.x + u3.y, u1.y - u3.x);
        float2 o2 = csub(u0, u2);
        float2 o3 = make_float2(u1.x - u3.y, u1.y + u3.x);
        float2 w1, w2, w3, w4, w5, w6, w7;
        if (st == 0) {                           // dense twiddles: compute from w1
            w1 = tw[i];
            w2 = cmul(w1, w1); w3 = cmul(w2, w1); w4 = cmul(w2, w2);
            w5 = cmul(w3, w2); w6 = cmul(w3, w3); w7 = cmul(w4, w3);
        } else {                                 // broadcast-heavy: load
            w1 = tw[ps];     w2 = tw[2 * ps]; w3 = tw[3 * ps]; w4 = tw[4 * ps];
            w5 = tw[5 * ps]; w6 = tw[6 * ps]; w7 = tw[7 * ps];
        }
        const int o = i + 7 * ps;
        y[SWZ(o)]         = e0;
        y[SWZ(o +     s)] = cmul(w1, o0);
        y[SWZ(o + 2 * s)] = cmul(w2, e1);
        y[SWZ(o + 3 * s)] = cmul(w3, o1);
        y[SWZ(o + 4 * s)] = cmul(w4, e2);
        y[SWZ(o + 5 * s)] = cmul(w5, o2);
        y[SWZ(o + 6 * s)] = cmul(w6, e3);
        y[SWZ(o + 7 * s)] = cmul(w7, o3);
        __syncthreads();
        float2* t = x; x = y; y = t;
    }
    if (!FINAL_R2) return x;                     // caller combines (l, l+4096)
    #pragma unroll
    for (int r = 0; r < 4; ++r) {
        const int i = tid + r * 1024;
        float2 a = x[SWZ(i)], b = x[SWZ(i + 4096)];
        y[SWZ(i)]        = cadd(a, b);
        y[SWZ(i + 4096)] = csub(a, b);
    }
    __syncthreads();
    return y;
}

__global__ void twiddle_kernel(float2* __restrict__ tw) {
    int k = blockIdx.x * blockDim.x + threadIdx.x;
    if (k < NFFT) {
        float s, c;
        sincospif((float)k / 4096.0f, &s, &c);
        tw[k] = make_float2(c, -s);
    }
}

#define SMEM_FFT ((16384 + 8192) * (int)sizeof(float2))   // 196608 B

// ---- packed filter FFT: 2 channels per block; stores Hermitian half --------
__global__ void __launch_bounds__(1024, 1) filter_kernel(
    const float* __restrict__ hfilt, const float2* __restrict__ gtw,
    float2* __restrict__ Hf) {
    extern __shared__ float2 smf[];
    float2* buf0 = smf;
    float2* buf1 = smf + 8192;
    float2* tw   = smf + 16384;
    const int tid = threadIdx.x;
    const int d0  = blockIdx.x * 2;

    for (int k = tid; k < NFFT; k += 1024) tw[k] = gtw[k];
    for (int l = tid; l < 4096; l += 1024) {
        float dec = expf(-0.01f * (float)l);
        float2 h = *reinterpret_cast<const float2*>(hfilt + (size_t)l * D_DIM + d0);
        buf0[SWZ(l)] = make_float2(h.x * dec, h.y * dec);
    }
    __syncthreads();
    float2* Z = fft8192_r8<true, true>(buf0, buf1, tw, tid);

    float2* H0 = Hf + (size_t)d0 * NFFT;
    float2* H1 = H0 + NFFT;
    for (int k = tid; k <= 4096; k += 1024) {
        const int km = (NFFT - k) & (NFFT - 1);
        float2 zk = Z[SWZ(k)], zm = Z[SWZ(km)];
        H0[k] = make_float2(0.5f * (zk.x + zm.x), 0.5f * (zk.y - zm.y));
        H1[k] = make_float2(0.5f * (zk.y + zm.y), 0.5f * (zm.x - zk.x));
    }
}

// ---- packed conv + gate: 2 channels per block; output rounded to tf32 ------
__global__ void __launch_bounds__(1024, 1) conv_kernel(
    const float* __restrict__ vT, const float* __restrict__ uT,
    const float2* __restrict__ Hf, const float2* __restrict__ gtw,
    float* __restrict__ yT) {
    extern __shared__ float2 smf[];
    float2* buf0 = smf;
    float2* buf1 = smf + 8192;
    float2* tw   = smf + 16384;
    const int tid = threadIdx.x;
    const int b   = blockIdx.x >> 9;
    const int d0  = (blockIdx.x & 511) * 2;
    const size_t row = ((size_t)b * D_DIM + d0) * L_DIM;

    const float* v0 = vT + row;
    const float* v1 = v0 + L_DIM;
    for (int k = tid; k < NFFT; k += 1024) tw[k] = gtw[k];
    for (int l = tid; l < 4096; l += 1024)
        buf0[SWZ(l)] = make_float2(v0[l], v1[l]);
    __syncthreads();

    float2* Z = fft8192_r8<true, true>(buf0, buf1, tw, tid);   // Z in buf1

    const float2* H0 = Hf + (size_t)d0 * NFFT;
    const float2* H1 = H0 + NFFT;
    for (int k = tid; k <= 4096; k += 1024) {
        const int km = (NFFT - k) & (NFFT - 1);
        float2 zk = Z[SWZ(k)], zm = Z[SWZ(km)];
        float2 vv0 = make_float2(0.5f * (zk.x + zm.x), 0.5f * (zk.y - zm.y));
        float2 vv1 = make_float2(0.5f * (zk.y + zm.y), 0.5f * (zm.x - zk.x));
        float2 P = cmul(vv0, __ldg(H0 + k));
        float2 Q = cmul(vv1, __ldg(H1 + k));
        buf0[SWZ(k)]  = make_float2(P.x - Q.y, -(P.y + Q.x));
        buf0[SWZ(km)] = make_float2(P.x + Q.y,  (P.y - Q.x));
    }
    __syncthreads();

    // inverse FFT without the final radix-2: combine pairs in the epilogue
    float2* P = fft8192_r8<false, false>(buf0, buf1, tw, tid);

    const float* u0 = uT + row;
    const float* u1 = u0 + L_DIM;
    float* y0 = yT + row;
    float* y1 = y0 + L_DIM;
    const float inv = 1.0f / (float)NFFT;
    for (int l = tid; l < 4096; l += 1024) {
        float2 R = cadd(P[SWZ(l)], P[SWZ(l + 4096)]);
        y0[l] = __uint_as_float(f2tf( R.x * inv * u0[l]));
        y1[l] = __uint_as_float(f2tf(-R.y * inv * u1[l]));
    }
}

// ======================= launch =============================================
extern "C" void kernel_launch(void* const* d_in, const int* in_sizes, int n_in,
                              void* d_out, int out_size) {
    const float* x   = (const float*)d_in[0];
    const float* Wu  = (const float*)d_in[1];
    const float* bu  = (const float*)d_in[2];
    const float* Wv  = (const float*)d_in[3];
    const float* bv  = (const float*)d_in[4];
    const float* hfl = (const float*)d_in[5];
    const float* Wo  = (const float*)d_in[6];
    const float* bo  = (const float*)d_in[7];
    float* out = (float*)d_out;

    void *pU, *pV, *pX, *pW, *pH, *pT;
    cudaGetSymbolAddress(&pU, g_uT);
    cudaGetSymbolAddress(&pV, g_vT);
    cudaGetSymbolAddress(&pX, g_xr);
    cudaGetSymbolAddress(&pW, g_Wt);
    cudaGetSymbolAddress(&pH, g_Hf);
    cudaGetSymbolAddress(&pT, g_tw);
    float* Wt = (float*)pW;

    cudaFuncSetAttribute(filter_kernel, cudaFuncAttributeMaxDynamicSharedMemorySize, SMEM_FFT);
    cudaFuncSetAttribute(conv_kernel,   cudaFuncAttributeMaxDynamicSharedMemorySize, SMEM_FFT);
    cudaFuncSetAttribute(gemm_mma<0>, cudaFuncAttributeMaxDynamicSharedMemorySize, GEMM_SMEM_BYTES);
    cudaFuncSetAttribute(gemm_mma<1>, cudaFuncAttributeMaxDynamicSharedMemorySize, GEMM_SMEM_BYTES);

    twiddle_kernel<<<32, 256>>>((float2*)pT);

    round_tf32_k<<<16384, 256>>>(x, (float*)pX);

    dim3 tb(32, 8);
    transpose_k<<<dim3(32, 32, 1), tb>>>(Wu, Wt,                   1024, 1024);
    transpose_k<<<dim3(32, 32, 1), tb>>>(Wv, Wt + 1024 * 1024,     1024, 1024);
    transpose_k<<<dim3(32, 32, 1), tb>>>(Wo, Wt + 2 * 1024 * 1024, 1024, 1024);

    filter_kernel<<<D_DIM / 2, 1024, SMEM_FFT>>>(hfl, (const float2*)pT, (float2*)pH);

    // GEMM1: uT/vT[b,e,l]  (i = e rows from Wt, j = m rows from rounded x)
    gemm_mma<0><<<dim3(128, 8), 256, GEMM_SMEM_BYTES>>>(Wt,               (const float*)pX, bu, (float*)pU);
    gemm_mma<0><<<dim3(128, 8), 256, GEMM_SMEM_BYTES>>>(Wt + 1024 * 1024, (const float*)pX, bv, (float*)pV);

    // packed conv: g_vT (v) -> g_vT (yT, tf32-rounded), gated by g_uT (u)
    conv_kernel<<<B_DIM * D_DIM / 2, 1024, SMEM_FFT>>>(
        (const float*)pV, (const float*)pU, (const float2*)pH, (const float2*)pT, (float*)pV);

    // GEMM2: out[m,e] = y Wo + bo  (A read transposed from yT — no copy)
    gemm_mma<1><<<dim3(8, 128), 256, GEMM_SMEM_BYTES>>>(
        (const float*)pV, Wt + 2 * 1024 * 1024, bo, out);
}